// round 15
// baseline (speedup 1.0000x reference)
#include <cuda_runtime.h>
#include <cstdint>
#include <cstddef>

#define Bn 128
#define Tn 2048
#define Cn 128
#define TSTRIDE 132  // padded row stride for transposed transitions in smem (backward)
#define SEG 128
#define NSEG 16

// Scratch (device globals; no runtime alloc):
__device__ __align__(16) float g_alpha[(size_t)Bn * Tn * Cn];  // all forward alphas
__device__ int g_tags[(size_t)Bn * Tn];                         // staged tags (per-call)

__device__ __forceinline__ unsigned long long pack2(float lo, float hi) {
    unsigned long long r;
    asm("mov.b64 %0, {%1, %2};" : "=l"(r) : "f"(lo), "f"(hi));
    return r;
}
__device__ __forceinline__ unsigned long long add2(unsigned long long a, unsigned long long b) {
    unsigned long long r;
    asm("add.rn.f32x2 %0, %1, %2;" : "=l"(r) : "l"(a), "l"(b));
    return r;
}
__device__ __forceinline__ float lo32(unsigned long long v) {
    return __uint_as_float((unsigned)v);
}
__device__ __forceinline__ float hi32(unsigned long long v) {
    return __uint_as_float((unsigned)(v >> 32));
}

__device__ __forceinline__ float4 f4max(float4 a, float4 b) {
    return make_float4(fmaxf(a.x, b.x), fmaxf(a.y, b.y),
                       fmaxf(a.z, b.z), fmaxf(a.w, b.w));
}

// ============================ FORWARD ============================
// 128 threads, 1 class j per thread, all 128 i's in-thread, 8 rotating accumulators.
// Running pointers + clamp-free structure: zero per-step integer overhead beyond ++.
__global__ __launch_bounds__(128, 1)
void viterbi_fwd(const float* __restrict__ pot,
                 const float* __restrict__ trans) {
    __shared__ __align__(16) float sb[2][Cn];  // double-buffered alpha row

    const int b = blockIdx.x;
    const int j = threadIdx.x;

    // Transition column j in registers, packed: tr2[q] = (T[2q][j], T[2q+1][j]).
    unsigned long long tr2[64];
    #pragma unroll
    for (int q = 0; q < 64; ++q) {
        tr2[q] = pack2(trans[(2 * q) * Cn + j], trans[(2 * q + 1) * Cn + j]);
    }

    const float* potp = pot + (size_t)b * Tn * Cn + j;
    float* aout = g_alpha + (size_t)b * Tn * Cn + j;

    // t = 0
    {
        float a0 = potp[0];
        sb[0][j] = a0;
        aout[0] = a0;
    }

    // Potentials prefetch ring (distance 4): slot t&3 consumed at step t.
    float pr[4];
    pr[1] = potp[(size_t)1 * Cn];
    pr[2] = potp[(size_t)2 * Cn];
    pr[3] = potp[(size_t)3 * Cn];
    pr[0] = potp[(size_t)4 * Cn];

    const float* pp = potp + (size_t)5 * Cn;   // next prefetch target (t=1 -> pot[5])
    float* ap = aout + Cn;                      // alpha store for t=1

    __syncthreads();

    int p = 0;

    // One step. PF: compile-time prefetch switch (main loop guarantees validity).
    auto step = [&](int t, bool PF) {
        float potv = pr[t & 3];
        if (PF) {
            pr[t & 3] = *pp;
            pp += Cn;
        }

        const ulonglong2* ab = (const ulonglong2*)sb[p];
        float m[8];
        #pragma unroll
        for (int g = 0; g < 32; ++g) {
            ulonglong2 A = ab[g];  // broadcast LDS.128: alphas[4g .. 4g+3]
            unsigned long long s01 = add2(A.x, tr2[2 * g]);
            unsigned long long s23 = add2(A.y, tr2[2 * g + 1]);
            float q = fmaxf(fmaxf(lo32(s01), hi32(s01)), fmaxf(lo32(s23), hi32(s23)));
            if (g < 8) m[g] = q;                 // init (compile-time)
            else       m[g & 7] = fmaxf(m[g & 7], q);
        }
        float h0 = fmaxf(m[0], m[1]);
        float h1 = fmaxf(m[2], m[3]);
        float h2 = fmaxf(m[4], m[5]);
        float h3 = fmaxf(m[6], m[7]);
        float best = fmaxf(fmaxf(h0, h1), fmaxf(h2, h3));

        float alpha = best + potv;
        sb[p ^ 1][j] = alpha;     // STS (conflict-free)
        *ap = alpha;              // STG archive (coalesced 512B)
        ap += Cn;
        __syncthreads();
        p ^= 1;
    };

    // Main: t = 1 .. 2040 (510 branch-free blocks of 4; prefetch t+4 <= 2044 valid).
    for (int tb = 1; tb <= Tn - 11; tb += 4) {
        step(tb + 0, true);
        step(tb + 1, true);
        step(tb + 2, true);
        step(tb + 3, true);
    }
    // Prefetch tail: t = 2041..2043 (prefetch 2045..2047, valid, no clamp).
    step(Tn - 7, true);
    step(Tn - 6, true);
    step(Tn - 5, true);
    // Final: t = 2044..2047, no prefetch.
    step(Tn - 4, false);
    step(Tn - 3, false);
    step(Tn - 2, false);
    step(Tn - 1, false);
}

// ============================ BACKWARD (speculative segmented trace) ============================
__device__ __forceinline__ int warp_argmax4_smem(float4 v, int l, float* pad) {
    float m = fmaxf(fmaxf(v.x, v.y), fmaxf(v.z, v.w));
    pad[l] = m;
    __syncwarp();
    const float4* p4 = (const float4*)pad;
    float4 a = f4max(f4max(p4[0], p4[1]), f4max(p4[2], p4[3]));
    float4 c = f4max(a, f4max(f4max(p4[4], p4[5]), f4max(p4[6], p4[7])));
    float wm = fmaxf(fmaxf(c.x, c.y), fmaxf(c.z, c.w));

    int loc = (v.x == m) ? 0 : ((v.y == m) ? 1 : ((v.z == m) ? 2 : 3));

    unsigned ball = __ballot_sync(0xffffffffu, m == wm);
    int lane = __ffs(ball) - 1;
    int locw = __shfl_sync(0xffffffffu, loc, lane);
    return 4 * lane + locw;
}

__global__ __launch_bounds__(512, 1)
void viterbi_bwd(const float* __restrict__ trans,
                 float* __restrict__ out) {
    extern __shared__ float smem[];
    float* tT = smem;                              // [Cn][TSTRIDE]
    float* pads = smem + Cn * TSTRIDE;             // [NSEG][64] per-warp pads
    int* bguess = (int*)(pads + NSEG * 64);        // [NSEG] boundary tag guesses
    int* bnew = bguess + NSEG;                     // [NSEG] computed boundary tags
    int* chg = bnew + NSEG;                        // [1] changed flag

    const int b = blockIdx.x;
    const int tid = threadIdx.x;
    const int w = tid >> 5;      // warp = segment id (0..15)
    const int l = tid & 31;
    float* pad = pads + w * 64;  // 2x32 per warp (parity halves)

    // Build transposed transitions in smem (coalesced reads; 512 threads).
    {
        int j0 = tid & 127;
        int r = tid >> 7;  // 0..3
        #pragma unroll
        for (int k = 0; k < 32; ++k) {
            int i = r * 32 + k;
            tT[j0 * TSTRIDE + i] = trans[i * Cn + j0];
        }
    }

    const float4* arow = (const float4*)(g_alpha + (size_t)b * Tn * Cn);
    int* tg = g_tags + (size_t)b * Tn;
    float* ob = out + (size_t)b * Tn;

    // Initial boundary guesses: bguess[w] ~ argmax alpha[128w] (w=1..15).
    // Warp 15 computes the EXACT global seed: argmax alpha[Tn-1].
    int seed15 = 0;
    if (w >= 1) {
        float4 av = arow[(size_t)(w * SEG) * 32 + l];
        int g = warp_argmax4_smem(av, l, pad);
        if (l == 0) bguess[w] = g;
    }
    if (w == 15) {
        float4 av = arow[(size_t)(Tn - 1) * 32 + l];
        seed15 = warp_argmax4_smem(av, l, pad + 32);
        if (l == 0) tg[Tn - 1] = seed15;
    }
    __syncthreads();

    const int lo = w * SEG;
    const int hi = (w == 15) ? (Tn - 2) : (w * SEG + SEG - 1);

    int prev_seed = -1;

    // Segment trace from 'seed'. If CHECK and the chain re-joins the previously
    // staged tags (block-granular compare), returns -1 (leave bnew unchanged):
    // the tag chain is a deterministic function of the matching tag, so all
    // remaining staged tags are already exact. Otherwise returns tag at t=lo.
    auto run_seg = [&](int seed, bool check) -> int {
        int tag = seed;

        float4 pf[4];
        #pragma unroll
        for (int k = 0; k < 4; ++k) {
            int r = hi - k;
            pf[r & 3] = arow[(size_t)r * 32 + l];
        }

        int t = hi;
        for (; t >= lo + 3; t -= 4) {
            int old4 = 0;
            if (check) old4 = tg[t - 3];   // pre-block staged tag (broadcast LDG)
            #pragma unroll
            for (int u = 0; u < 4; ++u) {
                int tt = t - u;
                int slot = tt & 3;
                float4 a = pf[slot];
                int rn = max(tt - 4, 0);
                pf[slot] = arow[(size_t)rn * 32 + l];

                const float4* trow = (const float4*)(tT + tag * TSTRIDE);
                float4 tv = trow[l];
                float4 s = make_float4(a.x + tv.x, a.y + tv.y,
                                       a.z + tv.z, a.w + tv.w);
                tag = warp_argmax4_smem(s, l, pad + (tt & 1) * 32);
                if (l == 0) tg[tt] = tag;
            }
            if (check && tag == old4) return -1;   // converged (warp-uniform)
        }
        for (; t >= lo; --t) {
            int slot = t & 3;
            float4 a = pf[slot];
            const float4* trow = (const float4*)(tT + tag * TSTRIDE);
            float4 tv = trow[l];
            float4 s = make_float4(a.x + tv.x, a.y + tv.y,
                                   a.z + tv.z, a.w + tv.w);
            tag = warp_argmax4_smem(s, l, pad + (t & 1) * 32);
            if (l == 0) tg[t] = tag;
        }
        return tag;
    };

    for (int iter = 0; iter < NSEG; ++iter) {
        const int seed = (w == 15) ? seed15 : bguess[w + 1];
        const bool doit = (seed != prev_seed);   // warp-uniform
        prev_seed = seed;

        if (doit) {
            int res = run_seg(seed, iter > 0);
            if (l == 0 && res >= 0) bnew[w] = res;
        }
        __syncthreads();

        if (tid == 0) chg[0] = 0;
        __syncthreads();
        if (tid >= 1 && tid <= 15) {
            if (bnew[tid] != bguess[tid]) atomicOr(chg, 1);
        }
        __syncthreads();
        const int changed = chg[0];
        if (tid >= 1 && tid <= 15) bguess[tid] = bnew[tid];
        __syncthreads();
        if (!changed) break;   // fixpoint: staged tags identical to sequential trace
    }

    // Publish staged tags (written THIS call) to the output buffer.
    __syncthreads();
    for (int k = tid; k < Tn; k += 512) {
        ob[k] = (float)tg[k];
    }
}

extern "C" void kernel_launch(void* const* d_in, const int* in_sizes, int n_in,
                              void* d_out, int out_size) {
    const float* inputs = (const float*)d_in[0];       // [B, T, C] f32
    const float* transitions = (const float*)d_in[1];  // [C, C] f32
    float* out = (float*)d_out;                        // [B, T] f32 (tags)

    viterbi_fwd<<<Bn, 128>>>(inputs, transitions);

    const int bwd_smem = (Cn * TSTRIDE + NSEG * 64) * (int)sizeof(float)
                         + (2 * NSEG + 1) * (int)sizeof(int);  // ~72KB
    cudaFuncSetAttribute(viterbi_bwd, cudaFuncAttributeMaxDynamicSharedMemorySize, bwd_smem);
    viterbi_bwd<<<Bn, 512, bwd_smem>>>(transitions, out);
}

// round 16
// speedup vs baseline: 1.2164x; 1.2164x over previous
#include <cuda_runtime.h>
#include <cstdint>
#include <cstddef>

#define Bn 128
#define Tn 2048
#define Cn 128
#define TSTRIDE 132  // padded row stride for transposed transitions in smem (backward)
#define SEG 128
#define NSEG 16

// Scratch (device globals; no runtime alloc):
__device__ __align__(16) float g_alpha[(size_t)Bn * Tn * Cn];  // all forward alphas
__device__ int g_tags[(size_t)Bn * Tn];                         // staged tags (per-call)

__device__ __forceinline__ unsigned long long pack2(float lo, float hi) {
    unsigned long long r;
    asm("mov.b64 %0, {%1, %2};" : "=l"(r) : "f"(lo), "f"(hi));
    return r;
}
__device__ __forceinline__ unsigned long long add2(unsigned long long a, unsigned long long b) {
    unsigned long long r;
    asm("add.rn.f32x2 %0, %1, %2;" : "=l"(r) : "l"(a), "l"(b));
    return r;
}
__device__ __forceinline__ float lo32(unsigned long long v) {
    return __uint_as_float((unsigned)v);
}
__device__ __forceinline__ float hi32(unsigned long long v) {
    return __uint_as_float((unsigned)(v >> 32));
}

__device__ __forceinline__ float4 f4max(float4 a, float4 b) {
    return make_float4(fmaxf(a.x, b.x), fmaxf(a.y, b.y),
                       fmaxf(a.z, b.z), fmaxf(a.w, b.w));
}

// ============================ FORWARD (R12 — best known) ============================
// 128 threads, 1 class j per thread, all 128 i's in-thread (no shuffles in hot loop).
// 8 rotating max accumulators keep the dependent chain shallow.
__global__ __launch_bounds__(128, 1)
void viterbi_fwd(const float* __restrict__ pot,
                 const float* __restrict__ trans) {
    __shared__ __align__(16) float sb[2][Cn];  // double-buffered alpha row

    const int b = blockIdx.x;
    const int j = threadIdx.x;

    // Transition column j in registers, packed: tr2[q] = (T[2q][j], T[2q+1][j]).
    unsigned long long tr2[64];
    #pragma unroll
    for (int q = 0; q < 64; ++q) {
        tr2[q] = pack2(trans[(2 * q) * Cn + j], trans[(2 * q + 1) * Cn + j]);
    }

    const float* potp = pot + (size_t)b * Tn * Cn + j;
    float* aout = g_alpha + (size_t)b * Tn * Cn + j;

    // t = 0
    {
        float a0 = potp[0];
        sb[0][j] = a0;
        aout[0] = a0;
    }

    // Potentials prefetch ring (distance 4), clamped refills: branch-free forever.
    float pr[4];
    pr[1] = potp[(size_t)1 * Cn];
    pr[2] = potp[(size_t)2 * Cn];
    pr[3] = potp[(size_t)3 * Cn];
    pr[0] = potp[(size_t)4 * Cn];

    __syncthreads();

    int p = 0;

    auto step = [&](int t, bool PF) {
        float potv = pr[t & 3];
        if (PF) {
            pr[t & 3] = potp[(size_t)min(t + 4, Tn - 1) * Cn];
        }

        const ulonglong2* ab = (const ulonglong2*)sb[p];
        float m[8];
        #pragma unroll
        for (int g = 0; g < 32; ++g) {
            ulonglong2 A = ab[g];  // broadcast LDS.128: alphas[4g .. 4g+3]
            unsigned long long s01 = add2(A.x, tr2[2 * g]);
            unsigned long long s23 = add2(A.y, tr2[2 * g + 1]);
            float q = fmaxf(fmaxf(lo32(s01), hi32(s01)), fmaxf(lo32(s23), hi32(s23)));
            if (g < 8) m[g] = q;                 // init (compile-time)
            else       m[g & 7] = fmaxf(m[g & 7], q);
        }
        float h0 = fmaxf(m[0], m[1]);
        float h1 = fmaxf(m[2], m[3]);
        float h2 = fmaxf(m[4], m[5]);
        float h3 = fmaxf(m[6], m[7]);
        float best = fmaxf(fmaxf(h0, h1), fmaxf(h2, h3));

        float alpha = best + potv;
        sb[p ^ 1][j] = alpha;               // STS (conflict-free)
        aout[(size_t)t * Cn] = alpha;       // STG archive (coalesced 512B)
        __syncthreads();
        p ^= 1;
    };

    // Main: t = 1 .. 2044 (511 branch-free blocks of 4), tail 3 steps.
    for (int tb = 1; tb <= Tn - 7; tb += 4) {
        step(tb + 0, true);
        step(tb + 1, true);
        step(tb + 2, true);
        step(tb + 3, true);
    }
    step(Tn - 3, false);
    step(Tn - 2, false);
    step(Tn - 1, false);
}

// ============================ BACKWARD (R15 — best known) ============================
__device__ __forceinline__ int warp_argmax4_smem(float4 v, int l, float* pad) {
    float m = fmaxf(fmaxf(v.x, v.y), fmaxf(v.z, v.w));
    pad[l] = m;
    __syncwarp();
    const float4* p4 = (const float4*)pad;
    float4 a = f4max(f4max(p4[0], p4[1]), f4max(p4[2], p4[3]));
    float4 c = f4max(a, f4max(f4max(p4[4], p4[5]), f4max(p4[6], p4[7])));
    float wm = fmaxf(fmaxf(c.x, c.y), fmaxf(c.z, c.w));

    int loc = (v.x == m) ? 0 : ((v.y == m) ? 1 : ((v.z == m) ? 2 : 3));

    unsigned ball = __ballot_sync(0xffffffffu, m == wm);
    int lane = __ffs(ball) - 1;
    int locw = __shfl_sync(0xffffffffu, loc, lane);
    return 4 * lane + locw;
}

__global__ __launch_bounds__(512, 1)
void viterbi_bwd(const float* __restrict__ trans,
                 float* __restrict__ out) {
    extern __shared__ float smem[];
    float* tT = smem;                              // [Cn][TSTRIDE]
    float* pads = smem + Cn * TSTRIDE;             // [NSEG][64] per-warp pads
    int* bguess = (int*)(pads + NSEG * 64);        // [NSEG] boundary tag guesses
    int* bnew = bguess + NSEG;                     // [NSEG] computed boundary tags
    int* chg = bnew + NSEG;                        // [1] changed flag

    const int b = blockIdx.x;
    const int tid = threadIdx.x;
    const int w = tid >> 5;      // warp = segment id (0..15)
    const int l = tid & 31;
    float* pad = pads + w * 64;  // 2x32 per warp (parity halves)

    // Build transposed transitions in smem (coalesced reads; 512 threads).
    {
        int j0 = tid & 127;
        int r = tid >> 7;  // 0..3
        #pragma unroll
        for (int k = 0; k < 32; ++k) {
            int i = r * 32 + k;
            tT[j0 * TSTRIDE + i] = trans[i * Cn + j0];
        }
    }

    const float4* arow = (const float4*)(g_alpha + (size_t)b * Tn * Cn);
    int* tg = g_tags + (size_t)b * Tn;
    float* ob = out + (size_t)b * Tn;

    // Initial boundary guesses: bguess[w] ~ argmax alpha[128w] (w=1..15).
    // Warp 15 computes the EXACT global seed: argmax alpha[Tn-1].
    int seed15 = 0;
    if (w >= 1) {
        float4 av = arow[(size_t)(w * SEG) * 32 + l];
        int g = warp_argmax4_smem(av, l, pad);
        if (l == 0) bguess[w] = g;
    }
    if (w == 15) {
        float4 av = arow[(size_t)(Tn - 1) * 32 + l];
        seed15 = warp_argmax4_smem(av, l, pad + 32);
        if (l == 0) tg[Tn - 1] = seed15;
    }
    __syncthreads();

    const int lo = w * SEG;
    const int hi = (w == 15) ? (Tn - 2) : (w * SEG + SEG - 1);

    int prev_seed = -1;

    // Segment trace from 'seed'. If CHECK and the chain re-joins the previously
    // staged tags (block-granular compare), returns -1 (leave bnew unchanged):
    // the tag chain is a deterministic function of the matching tag, so all
    // remaining staged tags are already exact. Otherwise returns tag at t=lo.
    auto run_seg = [&](int seed, bool check) -> int {
        int tag = seed;

        float4 pf[4];
        #pragma unroll
        for (int k = 0; k < 4; ++k) {
            int r = hi - k;
            pf[r & 3] = arow[(size_t)r * 32 + l];
        }

        int t = hi;
        for (; t >= lo + 3; t -= 4) {
            int old4 = 0;
            if (check) old4 = tg[t - 3];   // pre-block staged tag (broadcast LDG)
            #pragma unroll
            for (int u = 0; u < 4; ++u) {
                int tt = t - u;
                int slot = tt & 3;
                float4 a = pf[slot];
                int rn = max(tt - 4, 0);
                pf[slot] = arow[(size_t)rn * 32 + l];

                const float4* trow = (const float4*)(tT + tag * TSTRIDE);
                float4 tv = trow[l];
                float4 s = make_float4(a.x + tv.x, a.y + tv.y,
                                       a.z + tv.z, a.w + tv.w);
                tag = warp_argmax4_smem(s, l, pad + (tt & 1) * 32);
                if (l == 0) tg[tt] = tag;
            }
            if (check && tag == old4) return -1;   // converged (warp-uniform)
        }
        for (; t >= lo; --t) {
            int slot = t & 3;
            float4 a = pf[slot];
            const float4* trow = (const float4*)(tT + tag * TSTRIDE);
            float4 tv = trow[l];
            float4 s = make_float4(a.x + tv.x, a.y + tv.y,
                                   a.z + tv.z, a.w + tv.w);
            tag = warp_argmax4_smem(s, l, pad + (t & 1) * 32);
            if (l == 0) tg[t] = tag;
        }
        return tag;
    };

    for (int iter = 0; iter < NSEG; ++iter) {
        const int seed = (w == 15) ? seed15 : bguess[w + 1];
        const bool doit = (seed != prev_seed);   // warp-uniform
        prev_seed = seed;

        if (doit) {
            int res = run_seg(seed, iter > 0);
            if (l == 0 && res >= 0) bnew[w] = res;
        }
        __syncthreads();

        if (tid == 0) chg[0] = 0;
        __syncthreads();
        if (tid >= 1 && tid <= 15) {
            if (bnew[tid] != bguess[tid]) atomicOr(chg, 1);
        }
        __syncthreads();
        const int changed = chg[0];
        if (tid >= 1 && tid <= 15) bguess[tid] = bnew[tid];
        __syncthreads();
        if (!changed) break;   // fixpoint: staged tags identical to sequential trace
    }

    // Publish staged tags (written THIS call) to the output buffer.
    __syncthreads();
    for (int k = tid; k < Tn; k += 512) {
        ob[k] = (float)tg[k];
    }
}

extern "C" void kernel_launch(void* const* d_in, const int* in_sizes, int n_in,
                              void* d_out, int out_size) {
    const float* inputs = (const float*)d_in[0];       // [B, T, C] f32
    const float* transitions = (const float*)d_in[1];  // [C, C] f32
    float* out = (float*)d_out;                        // [B, T] f32 (tags)

    viterbi_fwd<<<Bn, 128>>>(inputs, transitions);

    const int bwd_smem = (Cn * TSTRIDE + NSEG * 64) * (int)sizeof(float)
                         + (2 * NSEG + 1) * (int)sizeof(int);  // ~72KB
    cudaFuncSetAttribute(viterbi_bwd, cudaFuncAttributeMaxDynamicSharedMemorySize, bwd_smem);
    viterbi_bwd<<<Bn, 512, bwd_smem>>>(transitions, out);
}